// round 6
// baseline (speedup 1.0000x reference)
#include <cuda_runtime.h>
#include <cuda_bf16.h>
#include <cstdint>
#include <cstddef>

// ---------------- problem constants ----------------
static constexpr int B_  = 4;
static constexpr int N_  = 4096;   // Ns == Nt
static constexpr int F_  = 256;
static constexpr int FO_ = 64;
static constexpr int TM_ = 128;    // t rows per CTA

// ---------------- main-kernel smem map (bytes) ----------------
// [0,16K)   EB1 (4096 floats)
// [16K,32K) EB2
// [32K,96K) V tiles: 4 slots x 16KB (slot = hi 8K | lo 8K); epilogue: C-merge (32KB)
// [96K+2K]  sden2[2][128]
static constexpr int EB1O = 0;
static constexpr int EB2O = 16384;
static constexpr int VO   = 32768;
static constexpr int SDEN = 98304;
static constexpr int SMEM_MAIN = 98304 + 1024;

// K2 smem: ctx chunk [128][stride 66] + Ws chunk [64][64]
static constexpr int K2_CS_STRIDE = 66;
static constexpr int K2_WS_OFF = 128 * K2_CS_STRIDE * 4;
static constexpr int K2_SMEM  = K2_WS_OFF + 64 * 64 * 4;

// ---------------- device scratch (no allocation allowed) ----------------
__device__ float g_w2[F_];
__device__ float g_EA1[B_ * N_];
__device__ float g_EA2[B_ * N_];
__device__ float g_EB1[B_ * N_];
__device__ float g_EB2[B_ * N_];
__device__ __nv_bfloat16 g_Vhi[(size_t)B_ * N_ * FO_];
__device__ __nv_bfloat16 g_Vlo[(size_t)B_ * N_ * FO_];

// ---------------- helpers ----------------
__device__ __forceinline__ uint32_t smem_u32(const void* p) {
    uint32_t a;
    asm("{ .reg .u64 t; cvta.to.shared.u64 t, %1; cvt.u32.u64 %0, t; }" : "=r"(a) : "l"(p));
    return a;
}

// pack two fp32 into bf16x2 by truncation (hi parts): low half <- a, high half <- b
__device__ __forceinline__ uint32_t pack_hi(float a, float b) {
    uint32_t r;
    asm("prmt.b32 %0, %1, %2, 0x7632;" : "=r"(r)
        : "r"(__float_as_uint(a)), "r"(__float_as_uint(b)));
    return r;
}
// pack two fp32 into bf16x2 with rounding: low half <- a, high half <- b
__device__ __forceinline__ uint32_t pack_rn(float a, float b) {
    uint32_t r;
    asm("cvt.rn.bf16x2.f32 %0, %1, %2;" : "=r"(r) : "f"(b), "f"(a));
    return r;
}
__device__ __forceinline__ float trunc_bf16(float a) {
    return __uint_as_float(__float_as_uint(a) & 0xFFFF0000u);
}

__device__ __forceinline__ void ldsm4t(uint32_t* r, uint32_t addr) {
    asm volatile("ldmatrix.sync.aligned.m8n8.x4.trans.shared.b16 {%0,%1,%2,%3}, [%4];"
        : "=r"(r[0]), "=r"(r[1]), "=r"(r[2]), "=r"(r[3]) : "r"(addr));
}

__device__ __forceinline__ void mma16816(float* c, uint32_t a0, uint32_t a1, uint32_t a2, uint32_t a3,
                                         uint32_t b0, uint32_t b1) {
    asm volatile("mma.sync.aligned.m16n8k16.row.col.f32.bf16.bf16.f32 "
        "{%0,%1,%2,%3}, {%4,%5,%6,%7}, {%8,%9}, {%0,%1,%2,%3};"
        : "+f"(c[0]), "+f"(c[1]), "+f"(c[2]), "+f"(c[3])
        : "r"(a0), "r"(a1), "r"(a2), "r"(a3), "r"(b0), "r"(b1));
}

// ---------------- K1: w2 = Wt @ a[64:128] ----------------
__global__ void gat_k1(const float* __restrict__ Wt, const float* __restrict__ a) {
    int f = threadIdx.x;  // 256 threads
    float acc = 0.f;
    #pragma unroll 8
    for (int o = 0; o < FO_; o++) acc += Wt[f * FO_ + o] * a[FO_ + o];
    g_w2[f] = acc;
}

// ---------------- K2: V = ctx@Ws (bf16 hi/lo split) + EA1/EA2 ----------------
__global__ __launch_bounds__(256) void gat_k2(const float* __restrict__ ctx,
                                              const float* __restrict__ Ws,
                                              const float* __restrict__ a) {
    extern __shared__ char sm[];
    float* cs  = (float*)sm;                 // [128][stride 66]
    float* wss = (float*)(sm + K2_WS_OFF);   // [64][64]
    int tid = threadIdx.x;
    int g0 = blockIdx.x * 128;               // global row over B*N (== b*N + s)

    int rowT = tid >> 4, colT = tid & 15;
    int r0 = rowT * 8, n0 = colT * 4;
    float acc[8][4];
    #pragma unroll
    for (int i = 0; i < 8; i++)
        #pragma unroll
        for (int c = 0; c < 4; c++) acc[i][c] = 0.f;

    for (int ch = 0; ch < 4; ch++) {
        int fc = ch * 64;
        if (ch) __syncthreads();
        #pragma unroll
        for (int it = 0; it < 8; it++) {
            int lin = tid + it * 256;
            int f4 = lin & 15, r = lin >> 4;
            float4 v = *(const float4*)&ctx[(size_t)(g0 + r) * F_ + fc + f4 * 4];
            float* d = &cs[r * K2_CS_STRIDE + f4 * 4];
            d[0] = v.x; d[1] = v.y; d[2] = v.z; d[3] = v.w;
        }
        #pragma unroll
        for (int it = 0; it < 4; it++) {
            int lin = tid + it * 256;
            int n4 = lin & 15, f = lin >> 4;
            float4 v = *(const float4*)&Ws[(size_t)(fc + f) * FO_ + n4 * 4];
            *(float4*)&wss[f * FO_ + n4 * 4] = v;
        }
        __syncthreads();
        #pragma unroll 4
        for (int f = 0; f < 64; f++) {
            float4 w = *(const float4*)&wss[f * FO_ + n0];
            #pragma unroll
            for (int i = 0; i < 8; i++) {
                float c = cs[(r0 + i) * K2_CS_STRIDE + f];
                acc[i][0] += c * w.x; acc[i][1] += c * w.y;
                acc[i][2] += c * w.z; acc[i][3] += c * w.w;
            }
        }
    }
    __syncthreads();

    float a1c[4];
    #pragma unroll
    for (int c = 0; c < 4; c++) a1c[c] = a[n0 + c];
    float* red = (float*)sm;  // [128][16] reuse
    #pragma unroll
    for (int i = 0; i < 8; i++) {
        float part = acc[i][0] * a1c[0] + acc[i][1] * a1c[1]
                   + acc[i][2] * a1c[2] + acc[i][3] * a1c[3];
        // split V (truncation hi + rounded residual)
        float l0 = acc[i][0] - trunc_bf16(acc[i][0]);
        float l1 = acc[i][1] - trunc_bf16(acc[i][1]);
        float l2 = acc[i][2] - trunc_bf16(acc[i][2]);
        float l3 = acc[i][3] - trunc_bf16(acc[i][3]);
        uint2 hst = make_uint2(pack_hi(acc[i][0], acc[i][1]), pack_hi(acc[i][2], acc[i][3]));
        uint2 lst = make_uint2(pack_rn(l0, l1), pack_rn(l2, l3));
        size_t base = (size_t)(g0 + r0 + i) * FO_ + n0;
        *(uint2*)&g_Vhi[base] = hst;
        *(uint2*)&g_Vlo[base] = lst;
        red[(r0 + i) * 16 + colT] = part;
    }
    __syncthreads();
    if (tid < 128) {
        float s = 0.f;
        #pragma unroll
        for (int j = 0; j < 16; j++) s += red[tid * 16 + j];
        g_EA1[g0 + tid] = __expf(s);
        g_EA2[g0 + tid] = __expf(0.2f * s);
    }
}

// ---------------- K3: tB = h @ w2 -> EB1/EB2 ----------------
__global__ __launch_bounds__(256) void gat_k3(const float* __restrict__ h) {
    int tid = threadIdx.x;
    int lane = tid & 31, w = tid >> 5;
    int sg = blockIdx.x * 8 + w;  // global row over B*N
    const float4* hp = (const float4*)(h + (size_t)sg * F_);
    const float4* wp = (const float4*)g_w2;
    float4 x0 = hp[lane],       w0 = wp[lane];
    float4 x1 = hp[lane + 32],  w1 = wp[lane + 32];
    float d = x0.x * w0.x + x0.y * w0.y + x0.z * w0.z + x0.w * w0.w
            + x1.x * w1.x + x1.y * w1.y + x1.z * w1.z + x1.w * w1.w;
    #pragma unroll
    for (int off = 16; off > 0; off >>= 1) d += __shfl_xor_sync(0xffffffffu, d, off);
    if (lane == 0) {
        g_EB1[sg] = __expf(d);
        g_EB2[sg] = __expf(0.2f * d);
    }
}

// ---------------- main fused attention kernel (mma.sync) ----------------
__global__ __launch_bounds__(512, 1)
void gat_main(const int* __restrict__ adj, float* __restrict__ out) {
    extern __shared__ char sm[];
    uint32_t smb = smem_u32(sm);
    float* EB1s = (float*)(sm + EB1O);
    float* EB2s = (float*)(sm + EB2O);
    char*  Vsm  = sm + VO;
    float* sden2 = (float*)(sm + SDEN);   // [2][128]

    int tid = threadIdx.x;
    int l = tid & 31, wid = tid >> 5;
    int cta = blockIdx.x;
    int b = cta >> 5;
    int t0 = (cta & 31) * TM_;
    int bN = b * N_;

    // stage EB1/EB2 (whole batch row set) into smem
    {
        const float4* s1 = (const float4*)(g_EB1 + bN);
        const float4* s2 = (const float4*)(g_EB2 + bN);
        float4* d1 = (float4*)EB1s;
        float4* d2 = (float4*)EB2s;
        d1[tid] = s1[tid]; d1[tid + 512] = s1[tid + 512];
        d2[tid] = s2[tid]; d2[tid + 512] = s2[tid + 512];
    }

    int wm = wid & 7;        // row-group (rows 16*wm .. 16*wm+15)
    int kh = wid >> 3;       // 0: even s-blocks, 1: odd s-blocks
    int rl0 = wm * 16 + (l >> 2);           // local row (0..127), second row = +8
    float ea1_0 = g_EA1[bN + t0 + rl0],     ea2_0 = g_EA2[bN + t0 + rl0];
    float ea1_1 = g_EA1[bN + t0 + rl0 + 8], ea2_1 = g_EA2[bN + t0 + rl0 + 8];
    const int* adj0 = adj + (size_t)(bN + t0 + rl0) * N_;
    const int* adj1 = adj0 + (size_t)8 * N_;
    int cb = (l & 3) * 2;

    // V cooperative load mapping: 4 chunks/thread (hi/lo x 2 block-halves)
    int vrow = tid >> 3, vcc = tid & 7;
    uint32_t vdst_off = (uint32_t)(vrow * 128 + vcc * 16) ^ ((uint32_t)(vrow & 7) << 4);

    // ldmatrix lane geometry
    uint32_t krow = l & 15;
    uint32_t ncol2 = ((l >> 4) * 8) * 2;
    uint32_t swx = (krow & 7) << 4;
    uint32_t Vaddr = smb + VO;

    // ---- prologue: adj + V for j=0 ----
    int2 aj[4][4];
    {
        int s0 = kh * 64;
        #pragma unroll
        for (int kk = 0; kk < 4; kk++) {
            int c0 = s0 + kk * 16 + cb;
            aj[kk][0] = *(const int2*)(adj0 + c0);
            aj[kk][1] = *(const int2*)(adj0 + c0 + 8);
            aj[kk][2] = *(const int2*)(adj1 + c0);
            aj[kk][3] = *(const int2*)(adj1 + c0 + 8);
        }
        #pragma unroll
        for (int p = 0; p < 4; p++) {
            int half = p >> 1, hl = p & 1;
            int srow = half * 64 + vrow;
            const __nv_bfloat16* src = (hl ? g_Vlo : g_Vhi)
                + (size_t)(bN + srow) * FO_ + vcc * 8;
            int4 v = *(const int4*)src;
            *(int4*)(Vsm + half * 16384 + hl * 8192 + vdst_off) = v;
        }
    }
    __syncthreads();

    float C[8][4];
    #pragma unroll
    for (int f = 0; f < 8; f++)
        #pragma unroll
        for (int i = 0; i < 4; i++) C[f][i] = 0.f;
    float dacc0 = 0.f, dacc1 = 0.f;

    for (int j = 0; j < 32; j++) {
        int sj = (2 * j + kh) * 64;
        uint32_t Vb = Vaddr + (uint32_t)(((j & 1) * 2 + kh) * 16384);

        // issue V loads for j+1 (latency hidden under compute)
        int4 vld[4];
        int jn = (j < 31) ? j + 1 : j;
        #pragma unroll
        for (int p = 0; p < 4; p++) {
            int half = p >> 1, hl = p & 1;
            int srow = (2 * jn + half) * 64 + vrow;
            const __nv_bfloat16* src = (hl ? g_Vlo : g_Vhi)
                + (size_t)(bN + srow) * FO_ + vcc * 8;
            vld[p] = *(const int4*)src;
        }

        #pragma unroll
        for (int kk = 0; kk < 4; kk++) {
            int c0 = sj + kk * 16 + cb;
            float2 e1a = *(const float2*)&EB1s[c0];
            float2 e1b = *(const float2*)&EB1s[c0 + 8];
            float2 e2a = *(const float2*)&EB2s[c0];
            float2 e2b = *(const float2*)&EB2s[c0 + 8];
            int2 A00 = aj[kk][0], A0h = aj[kk][1];
            int2 A10 = aj[kk][2], A1h = aj[kk][3];

            // q0: (row0, c-lo)  q1: (row0, c-hi)  q2: (row1, c-lo)  q3: (row1, c-hi)
            float p, q, x0, x1;
            // q0
            p = ea1_0 * e1a.x; q = ea2_0 * e2a.x; x0 = (p > 1.f) ? p : q; x0 = (A00.x > 0) ? x0 : 0.f;
            p = ea1_0 * e1a.y; q = ea2_0 * e2a.y; x1 = (p > 1.f) ? p : q; x1 = (A00.y > 0) ? x1 : 0.f;
            uint32_t hi0 = pack_hi(x0, x1);
            uint32_t lo0 = pack_rn(x0 - trunc_bf16(x0), x1 - trunc_bf16(x1));
            dacc0 += x0 + x1;
            // q1
            p = ea1_0 * e1b.x; q = ea2_0 * e2b.x; x0 = (p > 1.f) ? p : q; x0 = (A0h.x > 0) ? x0 : 0.f;
            p = ea1_0 * e1b.y; q = ea2_0 * e2b.y; x1 = (p > 1.f) ? p : q; x1 = (A0h.y > 0) ? x1 : 0.f;
            uint32_t hi2 = pack_hi(x0, x1);
            uint32_t lo2 = pack_rn(x0 - trunc_bf16(x0), x1 - trunc_bf16(x1));
            dacc0 += x0 + x1;
            // q2
            p = ea1_1 * e1a.x; q = ea2_1 * e2a.x; x0 = (p > 1.f) ? p : q; x0 = (A10.x > 0) ? x0 : 0.f;
            p = ea1_1 * e1a.y; q = ea2_1 * e2a.y; x1 = (p > 1.f) ? p : q; x1 = (A10.y > 0) ? x1 : 0.f;
            uint32_t hi1 = pack_hi(x0, x1);
            uint32_t lo1 = pack_rn(x0 - trunc_bf16(x0), x1 - trunc_bf16(x1));
            dacc1 += x0 + x1;
            // q3
            p = ea1_1 * e1b.x; q = ea2_1 * e2b.x; x0 = (p > 1.f) ? p : q; x0 = (A1h.x > 0) ? x0 : 0.f;
            p = ea1_1 * e1b.y; q = ea2_1 * e2b.y; x1 = (p > 1.f) ? p : q; x1 = (A1h.y > 0) ? x1 : 0.f;
            uint32_t hi3 = pack_hi(x0, x1);
            uint32_t lo3 = pack_rn(x0 - trunc_bf16(x0), x1 - trunc_bf16(x1));
            dacc1 += x0 + x1;

            #pragma unroll
            for (int ng = 0; ng < 4; ng++) {
                uint32_t off = (uint32_t)(kk * 2048 + ng * 32) + krow * 128 + ncol2;
                off ^= swx;
                uint32_t bh[4], bl[4];
                ldsm4t(bh, Vb + off);
                ldsm4t(bl, Vb + 8192 + off);
                mma16816(C[2 * ng],     hi0, hi1, hi2, hi3, bh[0], bh[1]);
                mma16816(C[2 * ng + 1], hi0, hi1, hi2, hi3, bh[2], bh[3]);
                mma16816(C[2 * ng],     lo0, lo1, lo2, lo3, bh[0], bh[1]);
                mma16816(C[2 * ng + 1], lo0, lo1, lo2, lo3, bh[2], bh[3]);
                mma16816(C[2 * ng],     hi0, hi1, hi2, hi3, bl[0], bl[1]);
                mma16816(C[2 * ng + 1], hi0, hi1, hi2, hi3, bl[2], bl[3]);
            }
        }

        // prefetch adj for j+1
        int sn = (j < 31) ? sj + 128 : sj;
        #pragma unroll
        for (int kk = 0; kk < 4; kk++) {
            int c0 = sn + kk * 16 + cb;
            aj[kk][0] = *(const int2*)(adj0 + c0);
            aj[kk][1] = *(const int2*)(adj0 + c0 + 8);
            aj[kk][2] = *(const int2*)(adj1 + c0);
            aj[kk][3] = *(const int2*)(adj1 + c0 + 8);
        }
        // commit V for j+1
        {
            char* Vd = Vsm + (size_t)(((j + 1) & 1) * 2) * 16384;
            #pragma unroll
            for (int p = 0; p < 4; p++) {
                int half = p >> 1, hl = p & 1;
                *(int4*)(Vd + half * 16384 + hl * 8192 + vdst_off) = vld[p];
            }
        }
        __syncthreads();
    }

    // ---- epilogue ----
    // deterministic denominator reduction
    dacc0 += __shfl_xor_sync(0xffffffffu, dacc0, 1);
    dacc0 += __shfl_xor_sync(0xffffffffu, dacc0, 2);
    dacc1 += __shfl_xor_sync(0xffffffffu, dacc1, 1);
    dacc1 += __shfl_xor_sync(0xffffffffu, dacc1, 2);
    if ((l & 3) == 0) {
        sden2[kh * 128 + rl0]     = dacc0;
        sden2[kh * 128 + rl0 + 8] = dacc1;
    }
    __syncthreads();

    // merge the two K-half accumulators through SMEM (reuse V area)
    float4* cm = (float4*)(sm + VO);
    if (kh == 1) {
        #pragma unroll
        for (int f = 0; f < 8; f++)
            cm[(wm * 8 + f) * 32 + l] = make_float4(C[f][0], C[f][1], C[f][2], C[f][3]);
    }
    __syncthreads();
    if (kh == 0) {
        float rd0 = 1.f / (sden2[rl0] + sden2[128 + rl0]);
        float rd1 = 1.f / (sden2[rl0 + 8] + sden2[128 + rl0 + 8]);
        float* o0 = out + (size_t)(bN + t0 + rl0) * FO_ + cb;
        float* o1 = out + (size_t)(bN + t0 + rl0 + 8) * FO_ + cb;
        #pragma unroll
        for (int f = 0; f < 8; f++) {
            float4 v = cm[(wm * 8 + f) * 32 + l];
            float x0 = (C[f][0] + v.x) * rd0;
            float x1 = (C[f][1] + v.y) * rd0;
            float x2 = (C[f][2] + v.z) * rd1;
            float x3 = (C[f][3] + v.w) * rd1;
            x0 = (x0 > 0.f) ? x0 : 0.01f * x0;
            x1 = (x1 > 0.f) ? x1 : 0.01f * x1;
            x2 = (x2 > 0.f) ? x2 : 0.01f * x2;
            x3 = (x3 > 0.f) ? x3 : 0.01f * x3;
            *(float2*)(o0 + f * 8) = make_float2(x0, x1);
            *(float2*)(o1 + f * 8) = make_float2(x2, x3);
        }
    }
}

// ---------------- launcher ----------------
extern "C" void kernel_launch(void* const* d_in, const int* in_sizes, int n_in,
                              void* d_out, int out_size) {
    const float* h   = (const float*)d_in[0];
    const float* ctx = (const float*)d_in[1];
    const int*   adj = (const int*)d_in[2];
    const float* Ws  = (const float*)d_in[3];
    const float* Wt  = (const float*)d_in[4];
    const float* a   = (const float*)d_in[5];
    float* out = (float*)d_out;

    cudaFuncSetAttribute(gat_k2, cudaFuncAttributeMaxDynamicSharedMemorySize, K2_SMEM);
    cudaFuncSetAttribute(gat_main, cudaFuncAttributeMaxDynamicSharedMemorySize, SMEM_MAIN);

    gat_k1<<<1, 256>>>(Wt, a);
    gat_k2<<<(B_ * N_) / 128, 256, K2_SMEM>>>(ctx, Ws, a);
    gat_k3<<<(B_ * N_) / 8, 256>>>(h);
    gat_main<<<B_ * (N_ / TM_), 512, SMEM_MAIN>>>(adj, out);
}

// round 7
// speedup vs baseline: 1.3065x; 1.3065x over previous
#include <cuda_runtime.h>
#include <cuda_bf16.h>
#include <cstdint>
#include <cstddef>

static constexpr int B_  = 4;
static constexpr int N_  = 4096;
static constexpr int F_  = 256;
static constexpr int FO_ = 64;
static constexpr int TM_ = 128;

// main smem: EB1 16K | EB2 16K | V dbl-buf 2x64K (hi32K+lo32K) | sden 2K
static constexpr int EB1O = 0;
static constexpr int EB2O = 16384;
static constexpr int VO   = 32768;
static constexpr int SDEN = 163840;
static constexpr int SMEM_MAIN = 165888;

static constexpr int K2_CS_STRIDE = 66;
static constexpr int K2_WS_OFF = 128 * K2_CS_STRIDE * 4;
static constexpr int K2_SMEM  = K2_WS_OFF + 64 * 64 * 4;

__device__ float g_w2[F_];
__device__ float g_EA1[B_ * N_];
__device__ float g_EA2[B_ * N_];
__device__ float g_EB1[B_ * N_];
__device__ float g_EB2[B_ * N_];
__device__ __nv_bfloat16 g_Vhi[(size_t)B_ * N_ * FO_];
__device__ __nv_bfloat16 g_Vlo[(size_t)B_ * N_ * FO_];

__device__ __forceinline__ uint32_t smem_u32(const void* p) {
    uint32_t a;
    asm("{ .reg .u64 t; cvta.to.shared.u64 t, %1; cvt.u32.u64 %0, t; }" : "=r"(a) : "l"(p));
    return a;
}
__device__ __forceinline__ uint32_t pack_hi(float a, float b) {
    uint32_t r;
    asm("prmt.b32 %0, %1, %2, 0x7632;" : "=r"(r)
        : "r"(__float_as_uint(a)), "r"(__float_as_uint(b)));
    return r;
}
__device__ __forceinline__ uint32_t pack_rn(float a, float b) {
    uint32_t r;
    asm("cvt.rn.bf16x2.f32 %0, %1, %2;" : "=r"(r) : "f"(b), "f"(a));
    return r;
}
__device__ __forceinline__ float trunc_bf16(float a) {
    return __uint_as_float(__float_as_uint(a) & 0xFFFF0000u);
}
__device__ __forceinline__ void ldsm4t(uint32_t* r, uint32_t addr) {
    asm volatile("ldmatrix.sync.aligned.m8n8.x4.trans.shared.b16 {%0,%1,%2,%3}, [%4];"
        : "=r"(r[0]), "=r"(r[1]), "=r"(r[2]), "=r"(r[3]) : "r"(addr));
}
__device__ __forceinline__ void mma16816(float* c, uint32_t a0, uint32_t a1, uint32_t a2, uint32_t a3,
                                         uint32_t b0, uint32_t b1) {
    asm volatile("mma.sync.aligned.m16n8k16.row.col.f32.bf16.bf16.f32 "
        "{%0,%1,%2,%3}, {%4,%5,%6,%7}, {%8,%9}, {%0,%1,%2,%3};"
        : "+f"(c[0]), "+f"(c[1]), "+f"(c[2]), "+f"(c[3])
        : "r"(a0), "r"(a1), "r"(a2), "r"(a3), "r"(b0), "r"(b1));
}
__device__ __forceinline__ void cp16(uint32_t dst, const void* src) {
    asm volatile("cp.async.cg.shared.global [%0], [%1], 16;" :: "r"(dst), "l"(src) : "memory");
}
__device__ __forceinline__ void cp_commit() { asm volatile("cp.async.commit_group;" ::: "memory"); }
template <int NW>
__device__ __forceinline__ void cp_wait() { asm volatile("cp.async.wait_group %0;" :: "n"(NW) : "memory"); }

// ---------------- K1 ----------------
__global__ void gat_k1(const float* __restrict__ Wt, const float* __restrict__ a) {
    int f = threadIdx.x;
    float acc = 0.f;
    #pragma unroll 8
    for (int o = 0; o < FO_; o++) acc += Wt[f * FO_ + o] * a[FO_ + o];
    g_w2[f] = acc;
}

// ---------------- K2: V (hi/lo) + EA ----------------
__global__ __launch_bounds__(256) void gat_k2(const float* __restrict__ ctx,
                                              const float* __restrict__ Ws,
                                              const float* __restrict__ a) {
    extern __shared__ char sm[];
    float* cs  = (float*)sm;
    float* wss = (float*)(sm + K2_WS_OFF);
    int tid = threadIdx.x;
    int g0 = blockIdx.x * 128;
    int rowT = tid >> 4, colT = tid & 15;
    int r0 = rowT * 8, n0 = colT * 4;
    float acc[8][4];
    #pragma unroll
    for (int i = 0; i < 8; i++)
        #pragma unroll
        for (int c = 0; c < 4; c++) acc[i][c] = 0.f;

    for (int ch = 0; ch < 4; ch++) {
        int fc = ch * 64;
        if (ch) __syncthreads();
        #pragma unroll
        for (int it = 0; it < 8; it++) {
            int lin = tid + it * 256;
            int f4 = lin & 15, r = lin >> 4;
            float4 v = *(const float4*)&ctx[(size_t)(g0 + r) * F_ + fc + f4 * 4];
            float* d = &cs[r * K2_CS_STRIDE + f4 * 4];
            d[0] = v.x; d[1] = v.y; d[2] = v.z; d[3] = v.w;
        }
        #pragma unroll
        for (int it = 0; it < 4; it++) {
            int lin = tid + it * 256;
            int n4 = lin & 15, f = lin >> 4;
            float4 v = *(const float4*)&Ws[(size_t)(fc + f) * FO_ + n4 * 4];
            *(float4*)&wss[f * FO_ + n4 * 4] = v;
        }
        __syncthreads();
        #pragma unroll 4
        for (int f = 0; f < 64; f++) {
            float4 w = *(const float4*)&wss[f * FO_ + n0];
            #pragma unroll
            for (int i = 0; i < 8; i++) {
                float c = cs[(r0 + i) * K2_CS_STRIDE + f];
                acc[i][0] += c * w.x; acc[i][1] += c * w.y;
                acc[i][2] += c * w.z; acc[i][3] += c * w.w;
            }
        }
    }
    __syncthreads();
    float a1c[4];
    #pragma unroll
    for (int c = 0; c < 4; c++) a1c[c] = a[n0 + c];
    float* red = (float*)sm;
    #pragma unroll
    for (int i = 0; i < 8; i++) {
        float part = acc[i][0] * a1c[0] + acc[i][1] * a1c[1]
                   + acc[i][2] * a1c[2] + acc[i][3] * a1c[3];
        float l0 = acc[i][0] - trunc_bf16(acc[i][0]);
        float l1 = acc[i][1] - trunc_bf16(acc[i][1]);
        float l2 = acc[i][2] - trunc_bf16(acc[i][2]);
        float l3 = acc[i][3] - trunc_bf16(acc[i][3]);
        uint2 hst = make_uint2(pack_hi(acc[i][0], acc[i][1]), pack_hi(acc[i][2], acc[i][3]));
        uint2 lst = make_uint2(pack_rn(l0, l1), pack_rn(l2, l3));
        size_t base = (size_t)(g0 + r0 + i) * FO_ + n0;
        *(uint2*)&g_Vhi[base] = hst;
        *(uint2*)&g_Vlo[base] = lst;
        red[(r0 + i) * 16 + colT] = part;
    }
    __syncthreads();
    if (tid < 128) {
        float s = 0.f;
        #pragma unroll
        for (int j = 0; j < 16; j++) s += red[tid * 16 + j];
        g_EA1[g0 + tid] = __expf(s);
        g_EA2[g0 + tid] = __expf(0.2f * s);
    }
}

// ---------------- K3: EB ----------------
__global__ __launch_bounds__(256) void gat_k3(const float* __restrict__ h) {
    int tid = threadIdx.x;
    int lane = tid & 31, w = tid >> 5;
    int sg = blockIdx.x * 8 + w;
    const float4* hp = (const float4*)(h + (size_t)sg * F_);
    const float4* wp = (const float4*)g_w2;
    float4 x0 = hp[lane],      w0 = wp[lane];
    float4 x1 = hp[lane + 32], w1 = wp[lane + 32];
    float d = x0.x * w0.x + x0.y * w0.y + x0.z * w0.z + x0.w * w0.w
            + x1.x * w1.x + x1.y * w1.y + x1.z * w1.z + x1.w * w1.w;
    #pragma unroll
    for (int off = 16; off > 0; off >>= 1) d += __shfl_xor_sync(0xffffffffu, d, off);
    if (lane == 0) {
        g_EB1[sg] = __expf(d);
        g_EB2[sg] = __expf(0.2f * d);
    }
}

// ---------------- main: 4 M-warps x 4 K-quarter warps ----------------
__global__ __launch_bounds__(512, 1)
void gat_main(const int* __restrict__ adj, float* __restrict__ out) {
    extern __shared__ char sm[];
    uint32_t smb = smem_u32(sm);
    float* EB1s = (float*)(sm + EB1O);
    float* EB2s = (float*)(sm + EB2O);
    float* sden = (float*)(sm + SDEN);   // [4][128]

    int tid = threadIdx.x;
    int l = tid & 31, wid = tid >> 5;
    int cta = blockIdx.x;
    int b = cta >> 5;
    int t0 = (cta & 31) * TM_;
    int bN = b * N_;
    int wm = wid & 3;    // rows wm*32 .. wm*32+31
    int kh = wid >> 2;   // 64-s quarter within each 256-s super-block

    {
        const float4* s1 = (const float4*)(g_EB1 + bN);
        const float4* s2 = (const float4*)(g_EB2 + bN);
        float4* d1 = (float4*)EB1s;
        float4* d2 = (float4*)EB2s;
        d1[tid] = s1[tid]; d1[tid + 512] = s1[tid + 512];
        d2[tid] = s2[tid]; d2[tid + 512] = s2[tid + 512];
    }

    int r0 = wm * 32 + (l >> 2);
    int cb = (l & 3) * 2;
    float ea1[4], ea2[4];
    #pragma unroll
    for (int p = 0; p < 4; p++) {
        ea1[p] = g_EA1[bN + t0 + r0 + p * 8];
        ea2[p] = g_EA2[bN + t0 + r0 + p * 8];
    }
    const int* adjB = adj + (size_t)(bN + t0 + r0) * N_;

    // cp.async V mapping: thread -> rows (tid>>3)+64*rho, 16B chunk (tid&7)
    int vr = tid >> 3, vc = tid & 7;
    uint32_t vdsw = (uint32_t)((vr * 128 + vc * 16) ^ ((vr & 7) << 4));
    const char* vsh = (const char*)(g_Vhi + ((size_t)bN + vr) * FO_ + vc * 8);
    const char* vsl = (const char*)(g_Vlo + ((size_t)bN + vr) * FO_ + vc * 8);

    // ldmatrix geometry (row = kh*64 + kk*16 + (l&15), colbyte = ng*32 + (l>>4)*16)
    uint32_t lb = (uint32_t)((kh * 64 + (l & 15)) * 128 + (l >> 4) * 16);
    uint32_t swx = (uint32_t)((l & 7) << 4);

    // prologue: V super-block 0
    {
        uint32_t d = smb + VO + vdsw;
        #pragma unroll
        for (int rho = 0; rho < 4; rho++) {
            cp16(d + rho * 8192, vsh + rho * 8192);
            cp16(d + 32768 + rho * 8192, vsl + rho * 8192);
        }
        cp_commit();
    }
    // adj prefetch (j=0, kk=0)
    int2 ajn[8];
    {
        int c0 = kh * 64 + cb;
        #pragma unroll
        for (int p = 0; p < 4; p++) {
            ajn[2 * p]     = *(const int2*)(adjB + (size_t)p * 8 * N_ + c0);
            ajn[2 * p + 1] = *(const int2*)(adjB + (size_t)p * 8 * N_ + c0 + 8);
        }
    }

    float C0[8][4], C1[8][4];
    #pragma unroll
    for (int f = 0; f < 8; f++)
        #pragma unroll
        for (int i = 0; i < 4; i++) { C0[f][i] = 0.f; C1[f][i] = 0.f; }
    float dden[4] = {0.f, 0.f, 0.f, 0.f};

    for (int j = 0; j < 16; j++) {
        if (j < 15) {
            uint32_t d = smb + VO + (uint32_t)(((j + 1) & 1) * 65536) + vdsw;
            const char* sh = vsh + (size_t)(j + 1) * 32768;
            const char* sl = vsl + (size_t)(j + 1) * 32768;
            #pragma unroll
            for (int rho = 0; rho < 4; rho++) {
                cp16(d + rho * 8192, sh + rho * 8192);
                cp16(d + 32768 + rho * 8192, sl + rho * 8192);
            }
            cp_commit();
            cp_wait<1>();
        } else {
            cp_wait<0>();
        }
        __syncthreads();

        uint32_t vbhi = smb + VO + (uint32_t)((j & 1) * 65536);
        uint32_t vblo = vbhi + 32768;
        int sj = j * 256 + kh * 64;

        #pragma unroll
        for (int kk = 0; kk < 4; kk++) {
            int c0 = sj + kk * 16 + cb;
            float2 e1a = *(const float2*)&EB1s[c0];
            float2 e1b = *(const float2*)&EB1s[c0 + 8];
            float2 e2a = *(const float2*)&EB2s[c0];
            float2 e2b = *(const float2*)&EB2s[c0 + 8];

            uint32_t hA[4], hB[4], lA[4], lB[4];
            #pragma unroll
            for (int p = 0; p < 4; p++) {
                int2 A0 = ajn[2 * p], A1 = ajn[2 * p + 1];
                float p1, p2, x0, x1, x2, x3;
                p1 = ea1[p] * e1a.x; p2 = ea2[p] * e2a.x; x0 = (p1 > 1.f) ? p1 : p2; x0 = (A0.x > 0) ? x0 : 0.f;
                p1 = ea1[p] * e1a.y; p2 = ea2[p] * e2a.y; x1 = (p1 > 1.f) ? p1 : p2; x1 = (A0.y > 0) ? x1 : 0.f;
                p1 = ea1[p] * e1b.x; p2 = ea2[p] * e2b.x; x2 = (p1 > 1.f) ? p1 : p2; x2 = (A1.x > 0) ? x2 : 0.f;
                p1 = ea1[p] * e1b.y; p2 = ea2[p] * e2b.y; x3 = (p1 > 1.f) ? p1 : p2; x3 = (A1.y > 0) ? x3 : 0.f;
                dden[p] += (x0 + x1) + (x2 + x3);
                hA[p] = pack_hi(x0, x1);
                lA[p] = pack_rn(x0 - trunc_bf16(x0), x1 - trunc_bf16(x1));
                hB[p] = pack_hi(x2, x3);
                lB[p] = pack_rn(x2 - trunc_bf16(x2), x3 - trunc_bf16(x3));
            }
            // prefetch adj for next kk (or next super-block)
            {
                int cn = (kk < 3) ? (c0 + 16) : ((j < 15) ? (c0 + 208) : c0);
                #pragma unroll
                for (int p = 0; p < 4; p++) {
                    ajn[2 * p]     = *(const int2*)(adjB + (size_t)p * 8 * N_ + cn);
                    ajn[2 * p + 1] = *(const int2*)(adjB + (size_t)p * 8 * N_ + cn + 8);
                }
            }
            uint32_t ob = lb + (uint32_t)(kk * 2048);
            #pragma unroll
            for (int ng = 0; ng < 4; ng++) {
                uint32_t off = (ob + (uint32_t)(ng * 32)) ^ swx;
                uint32_t bh[4], bl[4];
                ldsm4t(bh, vbhi + off);
                ldsm4t(bl, vblo + off);
                mma16816(C0[2 * ng],     hA[0], hA[1], hB[0], hB[1], bh[0], bh[1]);
                mma16816(C1[2 * ng],     hA[2], hA[3], hB[2], hB[3], bh[0], bh[1]);
                mma16816(C0[2 * ng + 1], hA[0], hA[1], hB[0], hB[1], bh[2], bh[3]);
                mma16816(C1[2 * ng + 1], hA[2], hA[3], hB[2], hB[3], bh[2], bh[3]);
                mma16816(C0[2 * ng],     lA[0], lA[1], lB[0], lB[1], bh[0], bh[1]);
                mma16816(C1[2 * ng],     lA[2], lA[3], lB[2], lB[3], bh[0], bh[1]);
                mma16816(C0[2 * ng + 1], lA[0], lA[1], lB[0], lB[1], bh[2], bh[3]);
                mma16816(C1[2 * ng + 1], lA[2], lA[3], lB[2], lB[3], bh[2], bh[3]);
                mma16816(C0[2 * ng],     hA[0], hA[1], hB[0], hB[1], bl[0], bl[1]);
                mma16816(C1[2 * ng],     hA[2], hA[3], hB[2], hB[3], bl[0], bl[1]);
                mma16816(C0[2 * ng + 1], hA[0], hA[1], hB[0], hB[1], bl[2], bl[3]);
                mma16816(C1[2 * ng + 1], hA[2], hA[3], hB[2], hB[3], bl[2], bl[3]);
            }
        }
        __syncthreads();
    }

    // ---- epilogue ----
    #pragma unroll
    for (int p = 0; p < 4; p++) {
        dden[p] += __shfl_xor_sync(0xffffffffu, dden[p], 1);
        dden[p] += __shfl_xor_sync(0xffffffffu, dden[p], 2);
    }
    if ((l & 3) == 0) {
        #pragma unroll
        for (int p = 0; p < 4; p++) sden[kh * 128 + r0 + p * 8] = dden[p];
    }
    // kh=1..3 dump partials into V area: [kh-1][row][64] floats
    if (kh) {
        float* mb = (float*)(sm + VO) + (size_t)(kh - 1) * 8192;
        #pragma unroll
        for (int g = 0; g < 2; g++) {
            int rr = wm * 32 + g * 16 + (l >> 2);
            float (*Cg)[4] = g ? C1 : C0;
            #pragma unroll
            for (int f = 0; f < 8; f++) {
                *(float2*)&mb[rr * 64 + f * 8 + cb]       = make_float2(Cg[f][0], Cg[f][1]);
                *(float2*)&mb[(rr + 8) * 64 + f * 8 + cb] = make_float2(Cg[f][2], Cg[f][3]);
            }
        }
    }
    __syncthreads();
    if (kh == 0) {
        const float* m1 = (const float*)(sm + VO);
        const float* m2 = m1 + 8192;
        const float* m3 = m2 + 8192;
        #pragma unroll
        for (int g = 0; g < 2; g++) {
            int rr = wm * 32 + g * 16 + (l >> 2);
            float rd0 = 1.f / (sden[rr] + sden[128 + rr] + sden[256 + rr] + sden[384 + rr]);
            int rs = rr + 8;
            float rd1 = 1.f / (sden[rs] + sden[128 + rs] + sden[256 + rs] + sden[384 + rs]);
            float (*Cg)[4] = g ? C1 : C0;
            float* o0 = out + (size_t)(bN + t0 + rr) * FO_ + cb;
            float* o1 = out + (size_t)(bN + t0 + rs) * FO_ + cb;
            #pragma unroll
            for (int f = 0; f < 8; f++) {
                int i0 = rr * 64 + f * 8 + cb, i1 = rs * 64 + f * 8 + cb;
                float x0 = (Cg[f][0] + m1[i0] + m2[i0] + m3[i0]) * rd0;
                float x1 = (Cg[f][1] + m1[i0 + 1] + m2[i0 + 1] + m3[i0 + 1]) * rd0;
                float x2 = (Cg[f][2] + m1[i1] + m2[i1] + m3[i1]) * rd1;
                float x3 = (Cg[f][3] + m1[i1 + 1] + m2[i1 + 1] + m3[i1 + 1]) * rd1;
                x0 = (x0 > 0.f) ? x0 : 0.01f * x0;
                x1 = (x1 > 0.f) ? x1 : 0.01f * x1;
                x2 = (x2 > 0.f) ? x2 : 0.01f * x2;
                x3 = (x3 > 0.f) ? x3 : 0.01f * x3;
                *(float2*)o0 = make_float2(x0, x1);
                *(float2*)o1 = make_float2(x2, x3);
                o0 += 8; o1 += 8;
            }
        }
    }
}

// ---------------- launcher ----------------
extern "C" void kernel_launch(void* const* d_in, const int* in_sizes, int n_in,
                              void* d_out, int out_size) {
    const float* h   = (const float*)d_in[0];
    const float* ctx = (const float*)d_in[1];
    const int*   adj = (const int*)d_in[2];
    const float* Ws  = (const float*)d_in[3];
    const float* Wt  = (const float*)d_in[4];
    const float* a   = (const float*)d_in[5];
    float* out = (float*)d_out;

    cudaFuncSetAttribute(gat_k2, cudaFuncAttributeMaxDynamicSharedMemorySize, K2_SMEM);
    cudaFuncSetAttribute(gat_main, cudaFuncAttributeMaxDynamicSharedMemorySize, SMEM_MAIN);

    gat_k1<<<1, 256>>>(Wt, a);
    gat_k2<<<(B_ * N_) / 128, 256, K2_SMEM>>>(ctx, Ws, a);
    gat_k3<<<(B_ * N_) / 8, 256>>>(h);
    gat_main<<<B_ * (N_ / TM_), 512, SMEM_MAIN>>>(adj, out);
}